// round 16
// baseline (speedup 1.0000x reference)
#include <cuda_runtime.h>
#include <math.h>

#define BN_EPS 1e-5f

// ---------------- device scratch (static; no allocation) ----------------
__device__ float g_C[(size_t)6*128*128*128];   // [l][b][n][m]  48 MB
__device__ float g_pre[128*128];               // out_x before BN (current layer)
__device__ float g_xeL[6*128*128];             // x_est per layer [l][b][m]
__device__ float g_part[6*1024];               // per-block loss partials
__device__ unsigned g_bar_cnt = 0;
__device__ volatile unsigned g_bar_gen = 0;
__device__ unsigned g_loss_tix = 0;            // last-block ticket

// ---------------- f32x2 packed helpers ----------------------------------
__device__ __forceinline__ unsigned long long pk2(float lo, float hi) {
    unsigned long long r;
    asm("mov.b64 %0, {%1, %2};" : "=l"(r) : "f"(lo), "f"(hi));
    return r;
}
__device__ __forceinline__ unsigned long long pk2s(float v) {
    unsigned long long r;
    asm("mov.b64 %0, {%1, %1};" : "=l"(r) : "f"(v));
    return r;
}
__device__ __forceinline__ void upk2(float& lo, float& hi, unsigned long long v) {
    asm("mov.b64 {%0, %1}, %2;" : "=f"(lo), "=f"(hi) : "l"(v));
}
__device__ __forceinline__ unsigned long long fma2_(unsigned long long a,
                                                   unsigned long long b,
                                                   unsigned long long c) {
    unsigned long long r;
    asm("fma.rn.f32x2 %0, %1, %2, %3;" : "=l"(r) : "l"(a), "l"(b), "l"(c));
    return r;
}

// ---------------- grid barrier (128 co-resident blocks, R13 proven) -----
__device__ __forceinline__ void gridbar(int nblocks)
{
    __syncthreads();
    if (threadIdx.x == 0) {
        __threadfence();
        unsigned gen = g_bar_gen;
        if (atomicAdd(&g_bar_cnt, 1u) == (unsigned)(nblocks - 1)) {
            g_bar_cnt = 0;
            __threadfence();
            g_bar_gen = gen + 1u;
        } else {
            while (g_bar_gen == gen) __nanosleep(32);
        }
        __threadfence();
    }
    __syncthreads();
}

// ---------------- reduce-scatter over 8-thread group --------------------
__device__ __forceinline__ float rscat8(float a0, float a1, float a2,
                                        float a3, float a4, float a5, int tk)
{
    const unsigned FULL = 0xffffffffu;
    float v6 = 0.f, v7 = 0.f;
    bool h4 = (tk & 4) != 0;
    float s0 = h4 ? a0 : a4, s1 = h4 ? a1 : a5;
    float s2 = h4 ? a2 : v6, s3 = h4 ? a3 : v7;
    float r0 = __shfl_xor_sync(FULL, s0, 4, 8);
    float r1 = __shfl_xor_sync(FULL, s1, 4, 8);
    float r2 = __shfl_xor_sync(FULL, s2, 4, 8);
    float r3 = __shfl_xor_sync(FULL, s3, 4, 8);
    float w0 = (h4 ? a4 : a0) + r0;
    float w1 = (h4 ? a5 : a1) + r1;
    float w2 = (h4 ? v6 : a2) + r2;
    float w3 = (h4 ? v7 : a3) + r3;
    bool h2 = (tk & 2) != 0;
    float t0 = h2 ? w0 : w2, t1 = h2 ? w1 : w3;
    float q0 = __shfl_xor_sync(FULL, t0, 2, 8);
    float q1 = __shfl_xor_sync(FULL, t1, 2, 8);
    float u0 = (h2 ? w2 : w0) + q0;
    float u1 = (h2 ? w3 : w1) + q1;
    bool h1 = (tk & 1) != 0;
    float p = h1 ? u0 : u1;
    float rr = __shfl_xor_sync(FULL, p, 1, 8);
    return (h1 ? u1 : u0) + rr;
}

// ---------------- K1: C_l[b,n,m] = sum_k BB[b,n,m,k]*wKL[l,k,m] ---------
// v5: 1 n-row per inner iter (smaller live set) -> 3 blocks/SM, 24 warps.
#define PLSTR 533
__global__ void __launch_bounds__(256, 3)
k_buildC(const float* __restrict__ BB, const float* __restrict__ wKL)
{
    const int m0   = blockIdx.x * 32;
    const int b    = blockIdx.y;
    const int mloc = threadIdx.x >> 3;   // 0..31
    const int tk   = threadIdx.x & 7;    // 0..7
    const int m    = m0 + mloc;
    const int wid  = threadIdx.x >> 5;
    const int lane = threadIdx.x & 31;

    __shared__ float buf[6*PLSTR + 33];

    // packed weights: j<4 -> k=4tk+j ; j>=4 -> k=32+4tk+(j-4)
    unsigned long long wp[3][8];
#pragma unroll
    for (int p = 0; p < 3; p++) {
#pragma unroll
        for (int j = 0; j < 8; j++) {
            int kidx = (j < 4) ? (tk*4 + j) : (32 + tk*4 + (j - 4));
            wp[p][j] = pk2(wKL[((2*p  )*64 + kidx)*128 + m],
                           wKL[((2*p+1)*64 + kidx)*128 + m]);
        }
    }

    const float4* BB4 = reinterpret_cast<const float4*>(BB)
                      + (size_t)b*262144 + (size_t)m*16;

    for (int nc = 0; nc < 8; nc++) {
#pragma unroll 2
        for (int nl = 0; nl < 16; nl++) {
            const int n = nc*16 + nl;
            const float4* rp = BB4 + (size_t)n*2048;
            float4 v0 = rp[tk], v1 = rp[tk + 8];

            unsigned long long a0 = 0ull, a1 = 0ull, a2 = 0ull;
            float fv[8] = {v0.x, v0.y, v0.z, v0.w, v1.x, v1.y, v1.z, v1.w};
#pragma unroll
            for (int j = 0; j < 8; j++) {
                unsigned long long xx = pk2s(fv[j]);
                a0 = fma2_(xx, wp[0][j], a0);
                a1 = fma2_(xx, wp[1][j], a1);
                a2 = fma2_(xx, wp[2][j], a2);
            }
            float c0, c1, c2, c3, c4, c5;
            upk2(c0, c1, a0); upk2(c2, c3, a1); upk2(c4, c5, a2);
            float r_n = rscat8(c0, c1, c2, c3, c4, c5, tk);
            if (tk < 6)
                buf[tk*PLSTR + nl*33 + mloc] = r_n;
        }
        __syncthreads();
        // flush 6 layers x 16 rows, coalesced: 8 warps x 12 rows
#pragma unroll
        for (int i = 0; i < 12; i++) {
            int r  = i*8 + wid;        // 0..95
            int l  = r >> 4;
            int nl = r & 15;
            g_C[(((size_t)l*128 + b)*128 + nc*16 + nl)*128 + m0 + lane]
                = buf[l*PLSTR + nl*33 + lane];
        }
        __syncthreads();
    }
}

// ---------------- K3: persistent layer chain (1024 thr: 8 per m) --------
__global__ void __launch_bounds__(1024, 1)
k_chain(const float* __restrict__ x0, const float* __restrict__ wx,
        const float* __restrict__ zB, const float* __restrict__ wKL,
        const float* __restrict__ gamma, const float* __restrict__ beta,
        float* __restrict__ out)
{
    const int b = blockIdx.x;
    const int t = threadIdx.x;
    const int m = t & 127;
    const int o = t >> 7;            // eighth index (0..7)
    __shared__ float xs[128];
    __shared__ float sp[1024];
    __shared__ float sq[1024];
    __shared__ float smu[128], srstd[128];
    __shared__ float sd[6*128];      // d[l][m] for this b

    // ---- compute d[l][m] = sum_k zB[b,m,k]*wKL[l,k,m] (o covers 8 k) ----
    {
        const float4* z4 = reinterpret_cast<const float4*>(zB + (size_t)b*8192)
                         + m*16 + o*2;
        float4 za = z4[0], zbv = z4[1];
        float zz[8] = {za.x,za.y,za.z,za.w, zbv.x,zbv.y,zbv.z,zbv.w};
        float p[6];
#pragma unroll
        for (int l = 0; l < 6; l++) {
            float acc = 0.f;
#pragma unroll
            for (int i = 0; i < 8; i++)
                acc = fmaf(zz[i], wKL[(l*64 + o*8 + i)*128 + m], acc);
            p[l] = acc;
        }
#pragma unroll
        for (int r = 0; r < 3; r++) {
            sp[t] = p[2*r];
            sq[t] = p[2*r + 1];
            __syncthreads();
            if (t < 128) {
                float sa = ((sp[m]+sp[m+128])+(sp[m+256]+sp[m+384]))
                         + ((sp[m+512]+sp[m+640])+(sp[m+768]+sp[m+896]));
                float sb = ((sq[m]+sq[m+128])+(sq[m+256]+sq[m+384]))
                         + ((sq[m+512]+sq[m+640])+(sq[m+768]+sq[m+896]));
                sd[(2*r    )*128 + m] = sa;
                sd[(2*r + 1)*128 + m] = sb;
            }
            __syncthreads();
        }
    }

    // ---- layer-0 pre (dense, eighth-split: 16 loads) ----
    {
        if (t < 128) xs[m] = x0[b*128 + m];
        __syncthreads();
        const float* Cb = g_C + (size_t)b*16384 + o*16*128 + m;
        float c[16];
#pragma unroll
        for (int j = 0; j < 16; j++) c[j] = Cb[j*128];
        float a0 = 0.f, a1 = 0.f, a2 = 0.f, a3 = 0.f;
#pragma unroll
        for (int j = 0; j < 16; j += 4) {
            a0 = fmaf(xs[o*16 + j    ], c[j    ], a0);
            a1 = fmaf(xs[o*16 + j + 1], c[j + 1], a1);
            a2 = fmaf(xs[o*16 + j + 2], c[j + 2], a2);
            a3 = fmaf(xs[o*16 + j + 3], c[j + 3], a3);
        }
        sp[t] = (a0 + a1) + (a2 + a3);
        __syncthreads();
        if (t < 128)
            g_pre[b*128 + m] = (((sp[m]+sp[m+128])+(sp[m+256]+sp[m+384]))
                              + ((sp[m+512]+sp[m+640])+(sp[m+768]+sp[m+896])))
                             + fmaf(xs[m], wx[m], -sd[m]);
    }
    gridbar(128);

    for (int l = 0; l < 6; l++) {
        // ---- redundant stats: full mu/rstd vector per block ----
        {
            const float* P = g_pre + o*16*128 + m;
            float s = 0.f, s2 = 0.f;
#pragma unroll
            for (int j = 0; j < 16; j++) {
                float v = P[j*128];
                s += v;
                s2 = fmaf(v, v, s2);
            }
            sp[t] = s; sq[t] = s2;
            __syncthreads();
            if (t < 128) {
                float a  = ((sp[m]+sp[m+128])+(sp[m+256]+sp[m+384]))
                         + ((sp[m+512]+sp[m+640])+(sp[m+768]+sp[m+896]));
                float a2 = ((sq[m]+sq[m+128])+(sq[m+256]+sq[m+384]))
                         + ((sq[m+512]+sq[m+640])+(sq[m+768]+sq[m+896]));
                float mu  = a * (1.f/128.f);
                float var = fmaf(-mu, mu, a2 * (1.f/128.f));
                smu[m]   = mu;
                srstd[m] = rsqrtf(var + BN_EPS);
            }
            __syncthreads();
        }

        // ---- BN + activation for this b (t<128) ----
        if (t < 128) {
            float v = g_pre[b*128 + m];
            v = fmaf(gamma[l*128 + m] * (v - smu[m]), srstd[m], beta[l*128 + m]);
            if (l < 5)
                v = fmaxf(v, 0.f);
            else
                v = -1.f + fmaxf(v + 0.5f, 0.f)*2.f - fmaxf(v - 0.5f, 0.f)*2.f;
            g_xeL[l*16384 + b*128 + m] = v;
            if (l == 5) out[b*128 + m] = v;
            xs[m] = v;
        }
        if (l == 5) break;
        __syncthreads();

        // ---- next-layer pre (dense, eighth-split) ----
        const int ln = l + 1;
        const float* Cb = g_C + ((size_t)ln*128 + b)*16384 + o*16*128 + m;
        float c[16];
#pragma unroll
        for (int j = 0; j < 16; j++) c[j] = Cb[j*128];
        float a0 = 0.f, a1 = 0.f, a2 = 0.f, a3 = 0.f;
#pragma unroll
        for (int j = 0; j < 16; j += 4) {
            a0 = fmaf(xs[o*16 + j    ], c[j    ], a0);
            a1 = fmaf(xs[o*16 + j + 1], c[j + 1], a1);
            a2 = fmaf(xs[o*16 + j + 2], c[j + 2], a2);
            a3 = fmaf(xs[o*16 + j + 3], c[j + 3], a3);
        }
        sp[t] = (a0 + a1) + (a2 + a3);
        __syncthreads();
        if (t < 128)
            g_pre[b*128 + m] = (((sp[m]+sp[m+128])+(sp[m+256]+sp[m+384]))
                              + ((sp[m+512]+sp[m+640])+(sp[m+768]+sp[m+896])))
                             + fmaf(xs[m], wx[ln*128 + m], -sd[ln*128 + m]);
        gridbar(128);
    }
}

// ---------------- K6: ALL-layer loss partials + final reduce ------------
__global__ void __launch_bounds__(256, 4)
k_loss_all(const float* __restrict__ B, const float* __restrict__ z,
           float* __restrict__ out,
           float s1, float s2, float s3, float s4, float s5)
{
    const int b   = blockIdx.y;
    const int ch  = blockIdx.x;
    const int tid = threadIdx.x;
    __shared__ float xs5[128][8];          // [n][l], padded
    __shared__ float wsum[5][8];
    __shared__ int   is_last;

    if (tid < 128) {
#pragma unroll
        for (int l = 0; l < 5; l++)
            xs5[tid][l] = g_xeL[(l+1)*16384 + b*128 + tid];
        xs5[tid][5] = 0.f; xs5[tid][6] = 0.f; xs5[tid][7] = 0.f;
    }
    __syncthreads();

    float acc[5][4];
#pragma unroll
    for (int l = 0; l < 5; l++)
#pragma unroll
        for (int j = 0; j < 4; j++) acc[l][j] = 0.f;

    const float4* Bb = reinterpret_cast<const float4*>(B)
                     + (size_t)b*262144 + ch*256 + tid;

    for (int n = 0; n < 128; n += 4) {
        float4 r0 = Bb[(size_t)(n  )*2048];
        float4 r1 = Bb[(size_t)(n+1)*2048];
        float4 r2 = Bb[(size_t)(n+2)*2048];
        float4 r3 = Bb[(size_t)(n+3)*2048];
#pragma unroll
        for (int j4 = 0; j4 < 4; j4++) {
            float4 rr = (j4 == 0) ? r0 : (j4 == 1) ? r1 : (j4 == 2) ? r2 : r3;
            const float4 xq = *reinterpret_cast<const float4*>(&xs5[n + j4][0]);
            const float x4 = xs5[n + j4][4];
            const float xl[5] = {xq.x, xq.y, xq.z, xq.w, x4};
#pragma unroll
            for (int l = 0; l < 5; l++) {
                acc[l][0] = fmaf(xl[l], rr.x, acc[l][0]);
                acc[l][1] = fmaf(xl[l], rr.y, acc[l][1]);
                acc[l][2] = fmaf(xl[l], rr.z, acc[l][2]);
                acc[l][3] = fmaf(xl[l], rr.w, acc[l][3]);
            }
        }
    }

    const float4 zv = reinterpret_cast<const float4*>(z)[(size_t)b*2048 + ch*256 + tid];
    const float zz[4] = {zv.x, zv.y, zv.z, zv.w};

#pragma unroll
    for (int l = 0; l < 5; l++) {
        float part = 0.f;
#pragma unroll
        for (int j = 0; j < 4; j++) {
            float e = zz[j] - acc[l][j];
            part = fmaf(e, e, part);
        }
#pragma unroll
        for (int o = 16; o > 0; o >>= 1)
            part += __shfl_down_sync(0xffffffffu, part, o);
        if ((tid & 31) == 0) wsum[l][tid >> 5] = part;
    }
    __syncthreads();
    if (tid == 0) {
#pragma unroll
        for (int l = 0; l < 5; l++) {
            float t = 0.f;
#pragma unroll
            for (int w = 0; w < 8; w++) t += wsum[l][w];
            g_part[(l+1)*1024 + b*8 + ch] = t;
        }
        __threadfence();
        unsigned tix = atomicAdd(&g_loss_tix, 1u);
        is_last = (tix == 1023u) ? 1 : 0;
        if (is_last) g_loss_tix = 0;   // self-reset for graph replay
    }
    __syncthreads();

    if (is_last) {
        __threadfence();               // all g_part writes now visible
        const int w    = tid >> 5;     // warp 0..7
        const int lane = tid & 31;
        if (tid == 0) out[16384] = 0.f;
        if (w < 5) {
            const float scl[5] = {s1, s2, s3, s4, s5};
            const float* P = g_part + (w + 1)*1024;
            float s = 0.f;
#pragma unroll
            for (int i = 0; i < 32; i++)
                s += P[i*32 + lane];
#pragma unroll
            for (int o = 16; o > 0; o >>= 1)
                s += __shfl_down_sync(0xffffffffu, s, o);
            if (lane == 0) out[16384 + w + 1] = scl[w] * s;
        }
    }
}

// ---------------- launch ------------------------------------------------
extern "C" void kernel_launch(void* const* d_in, const int* in_sizes, int n_in,
                              void* d_out, int out_size)
{
    (void)in_sizes; (void)n_in; (void)out_size;
    const float* BB    = (const float*)d_in[0];
    const float* zB    = (const float*)d_in[1];
    const float* z     = (const float*)d_in[3];
    const float* B     = (const float*)d_in[4];
    const float* x0    = (const float*)d_in[5];
    const float* w_x   = (const float*)d_in[6];
    const float* wKL   = (const float*)d_in[7];
    const float* gamma = (const float*)d_in[8];
    const float* beta  = (const float*)d_in[9];
    float* out = (float*)d_out;

    k_buildC<<<dim3(4,128), 256>>>(BB, wKL);
    k_chain<<<128, 1024>>>(x0, w_x, zB, wKL, gamma, beta, out);

    const float inv = 1.0f / 16384.0f;
    k_loss_all<<<dim3(8,128), 256>>>(B, z, out,
        10.0f * logf(2.0f) * inv,
        10.0f * logf(3.0f) * inv,
        10.0f * logf(4.0f) * inv,
        10.0f * logf(5.0f) * inv,
        10.0f * logf(6.0f) * inv);
}

// round 17
// speedup vs baseline: 1.3177x; 1.3177x over previous
#include <cuda_runtime.h>
#include <math.h>

#define BN_EPS 1e-5f

// ---------------- device scratch (static; no allocation) ----------------
__device__ float g_C[(size_t)6*128*128*128];   // [l][b][n][m]  48 MB
__device__ float g_pre[128*128];               // out_x before BN (current layer)
__device__ float g_xeL[6*128*128];             // x_est per layer [l][b][m]
__device__ float g_part[6*1024];               // per-block loss partials
__device__ unsigned g_bar_cnt = 0;
__device__ volatile unsigned g_bar_gen = 0;
__device__ unsigned g_loss_tix = 0;            // last-block ticket

// ---------------- f32x2 packed helpers ----------------------------------
__device__ __forceinline__ unsigned long long pk2(float lo, float hi) {
    unsigned long long r;
    asm("mov.b64 %0, {%1, %2};" : "=l"(r) : "f"(lo), "f"(hi));
    return r;
}
__device__ __forceinline__ unsigned long long pk2s(float v) {
    unsigned long long r;
    asm("mov.b64 %0, {%1, %1};" : "=l"(r) : "f"(v));
    return r;
}
__device__ __forceinline__ void upk2(float& lo, float& hi, unsigned long long v) {
    asm("mov.b64 {%0, %1}, %2;" : "=f"(lo), "=f"(hi) : "l"(v));
}
__device__ __forceinline__ unsigned long long fma2_(unsigned long long a,
                                                   unsigned long long b,
                                                   unsigned long long c) {
    unsigned long long r;
    asm("fma.rn.f32x2 %0, %1, %2, %3;" : "=l"(r) : "l"(a), "l"(b), "l"(c));
    return r;
}

// ---------------- grid barrier (128 co-resident blocks, R13 proven) -----
__device__ __forceinline__ void gridbar(int nblocks)
{
    __syncthreads();
    if (threadIdx.x == 0) {
        __threadfence();
        unsigned gen = g_bar_gen;
        if (atomicAdd(&g_bar_cnt, 1u) == (unsigned)(nblocks - 1)) {
            g_bar_cnt = 0;
            __threadfence();
            g_bar_gen = gen + 1u;
        } else {
            while (g_bar_gen == gen) __nanosleep(32);
        }
        __threadfence();
    }
    __syncthreads();
}

// ---------------- reduce-scatter over 8-thread group --------------------
__device__ __forceinline__ float rscat8(float a0, float a1, float a2,
                                        float a3, float a4, float a5, int tk)
{
    const unsigned FULL = 0xffffffffu;
    float v6 = 0.f, v7 = 0.f;
    bool h4 = (tk & 4) != 0;
    float s0 = h4 ? a0 : a4, s1 = h4 ? a1 : a5;
    float s2 = h4 ? a2 : v6, s3 = h4 ? a3 : v7;
    float r0 = __shfl_xor_sync(FULL, s0, 4, 8);
    float r1 = __shfl_xor_sync(FULL, s1, 4, 8);
    float r2 = __shfl_xor_sync(FULL, s2, 4, 8);
    float r3 = __shfl_xor_sync(FULL, s3, 4, 8);
    float w0 = (h4 ? a4 : a0) + r0;
    float w1 = (h4 ? a5 : a1) + r1;
    float w2 = (h4 ? v6 : a2) + r2;
    float w3 = (h4 ? v7 : a3) + r3;
    bool h2 = (tk & 2) != 0;
    float t0 = h2 ? w0 : w2, t1 = h2 ? w1 : w3;
    float q0 = __shfl_xor_sync(FULL, t0, 2, 8);
    float q1 = __shfl_xor_sync(FULL, t1, 2, 8);
    float u0 = (h2 ? w2 : w0) + q0;
    float u1 = (h2 ? w3 : w1) + q1;
    bool h1 = (tk & 1) != 0;
    float p = h1 ? u0 : u1;
    float rr = __shfl_xor_sync(FULL, p, 1, 8);
    return (h1 ? u1 : u0) + rr;
}

// ---------------- K1: C_l[b,n,m] = sum_k BB[b,n,m,k]*wKL[l,k,m] ---------
// R9/R15 8-lane, 2-rows-per-iter version (measured ~105us @ ~70% DRAM).
#define PLSTR 533
__global__ void __launch_bounds__(256, 2)
k_buildC(const float* __restrict__ BB, const float* __restrict__ wKL)
{
    const int m0   = blockIdx.x * 32;
    const int b    = blockIdx.y;
    const int mloc = threadIdx.x >> 3;   // 0..31
    const int tk   = threadIdx.x & 7;    // 0..7
    const int m    = m0 + mloc;
    const int wid  = threadIdx.x >> 5;
    const int lane = threadIdx.x & 31;

    __shared__ float buf[6*PLSTR + 33];

    // packed weights: j<4 -> k=4tk+j ; j>=4 -> k=32+4tk+(j-4)
    unsigned long long wp[3][8];
#pragma unroll
    for (int p = 0; p < 3; p++) {
#pragma unroll
        for (int j = 0; j < 8; j++) {
            int kidx = (j < 4) ? (tk*4 + j) : (32 + tk*4 + (j - 4));
            wp[p][j] = pk2(wKL[((2*p  )*64 + kidx)*128 + m],
                           wKL[((2*p+1)*64 + kidx)*128 + m]);
        }
    }

    const float4* BB4 = reinterpret_cast<const float4*>(BB)
                      + (size_t)b*262144 + (size_t)m*16;

    for (int nc = 0; nc < 8; nc++) {
#pragma unroll 2
        for (int nl = 0; nl < 16; nl += 2) {
            const int n = nc*16 + nl;
            const float4* rp = BB4 + (size_t)n*2048;
            float4 v0 = rp[tk],        v1 = rp[tk + 8];
            float4 u0 = rp[2048 + tk], u1 = rp[2056 + tk];

            unsigned long long a0 = 0ull, a1 = 0ull, a2 = 0ull;
            unsigned long long b0 = 0ull, b1 = 0ull, b2 = 0ull;
            float fv[8] = {v0.x, v0.y, v0.z, v0.w, v1.x, v1.y, v1.z, v1.w};
            float fu[8] = {u0.x, u0.y, u0.z, u0.w, u1.x, u1.y, u1.z, u1.w};
#pragma unroll
            for (int j = 0; j < 8; j++) {
                unsigned long long xx = pk2s(fv[j]);
                a0 = fma2_(xx, wp[0][j], a0);
                a1 = fma2_(xx, wp[1][j], a1);
                a2 = fma2_(xx, wp[2][j], a2);
                unsigned long long yy = pk2s(fu[j]);
                b0 = fma2_(yy, wp[0][j], b0);
                b1 = fma2_(yy, wp[1][j], b1);
                b2 = fma2_(yy, wp[2][j], b2);
            }
            float c0, c1, c2, c3, c4, c5;
            upk2(c0, c1, a0); upk2(c2, c3, a1); upk2(c4, c5, a2);
            float r_n  = rscat8(c0, c1, c2, c3, c4, c5, tk);
            upk2(c0, c1, b0); upk2(c2, c3, b1); upk2(c4, c5, b2);
            float r_n1 = rscat8(c0, c1, c2, c3, c4, c5, tk);
            if (tk < 6) {
                buf[tk*PLSTR + (nl    )*33 + mloc] = r_n;
                buf[tk*PLSTR + (nl + 1)*33 + mloc] = r_n1;
            }
        }
        __syncthreads();
        // flush 6 layers x 16 rows, coalesced: 8 warps x 12 rows
#pragma unroll
        for (int i = 0; i < 12; i++) {
            int r  = i*8 + wid;        // 0..95
            int l  = r >> 4;
            int nl = r & 15;
            g_C[(((size_t)l*128 + b)*128 + nc*16 + nl)*128 + m0 + lane]
                = buf[l*PLSTR + nl*33 + lane];
        }
        __syncthreads();
    }
}

// ---------------- K3: persistent layer chain (1024 thr: 8 per m) --------
__global__ void __launch_bounds__(1024, 1)
k_chain(const float* __restrict__ x0, const float* __restrict__ wx,
        const float* __restrict__ zB, const float* __restrict__ wKL,
        const float* __restrict__ gamma, const float* __restrict__ beta,
        float* __restrict__ out)
{
    const int b = blockIdx.x;
    const int t = threadIdx.x;
    const int m = t & 127;
    const int o = t >> 7;            // eighth index (0..7)
    __shared__ float xs[128];
    __shared__ float sp[1024];
    __shared__ float sq[1024];
    __shared__ float smu[128], srstd[128];
    __shared__ float sd[6*128];      // d[l][m] for this b

    // ---- compute d[l][m] = sum_k zB[b,m,k]*wKL[l,k,m] (o covers 8 k) ----
    {
        const float4* z4 = reinterpret_cast<const float4*>(zB + (size_t)b*8192)
                         + m*16 + o*2;
        float4 za = z4[0], zbv = z4[1];
        float zz[8] = {za.x,za.y,za.z,za.w, zbv.x,zbv.y,zbv.z,zbv.w};
        float p[6];
#pragma unroll
        for (int l = 0; l < 6; l++) {
            float acc = 0.f;
#pragma unroll
            for (int i = 0; i < 8; i++)
                acc = fmaf(zz[i], wKL[(l*64 + o*8 + i)*128 + m], acc);
            p[l] = acc;
        }
#pragma unroll
        for (int r = 0; r < 3; r++) {
            sp[t] = p[2*r];
            sq[t] = p[2*r + 1];
            __syncthreads();
            if (t < 128) {
                float sa = ((sp[m]+sp[m+128])+(sp[m+256]+sp[m+384]))
                         + ((sp[m+512]+sp[m+640])+(sp[m+768]+sp[m+896]));
                float sb = ((sq[m]+sq[m+128])+(sq[m+256]+sq[m+384]))
                         + ((sq[m+512]+sq[m+640])+(sq[m+768]+sq[m+896]));
                sd[(2*r    )*128 + m] = sa;
                sd[(2*r + 1)*128 + m] = sb;
            }
            __syncthreads();
        }
    }

    // ---- layer-0 pre (dense, eighth-split: 16 loads) ----
    {
        if (t < 128) xs[m] = x0[b*128 + m];
        __syncthreads();
        const float* Cb = g_C + (size_t)b*16384 + o*16*128 + m;
        float c[16];
#pragma unroll
        for (int j = 0; j < 16; j++) c[j] = Cb[j*128];
        float a0 = 0.f, a1 = 0.f, a2 = 0.f, a3 = 0.f;
#pragma unroll
        for (int j = 0; j < 16; j += 4) {
            a0 = fmaf(xs[o*16 + j    ], c[j    ], a0);
            a1 = fmaf(xs[o*16 + j + 1], c[j + 1], a1);
            a2 = fmaf(xs[o*16 + j + 2], c[j + 2], a2);
            a3 = fmaf(xs[o*16 + j + 3], c[j + 3], a3);
        }
        sp[t] = (a0 + a1) + (a2 + a3);
        __syncthreads();
        if (t < 128)
            g_pre[b*128 + m] = (((sp[m]+sp[m+128])+(sp[m+256]+sp[m+384]))
                              + ((sp[m+512]+sp[m+640])+(sp[m+768]+sp[m+896])))
                             + fmaf(xs[m], wx[m], -sd[m]);
    }
    gridbar(128);

    for (int l = 0; l < 6; l++) {
        // ---- redundant stats: full mu/rstd vector per block ----
        {
            const float* P = g_pre + o*16*128 + m;
            float s = 0.f, s2 = 0.f;
#pragma unroll
            for (int j = 0; j < 16; j++) {
                float v = P[j*128];
                s += v;
                s2 = fmaf(v, v, s2);
            }
            sp[t] = s; sq[t] = s2;
            __syncthreads();
            if (t < 128) {
                float a  = ((sp[m]+sp[m+128])+(sp[m+256]+sp[m+384]))
                         + ((sp[m+512]+sp[m+640])+(sp[m+768]+sp[m+896]));
                float a2 = ((sq[m]+sq[m+128])+(sq[m+256]+sq[m+384]))
                         + ((sq[m+512]+sq[m+640])+(sq[m+768]+sq[m+896]));
                float mu  = a * (1.f/128.f);
                float var = fmaf(-mu, mu, a2 * (1.f/128.f));
                smu[m]   = mu;
                srstd[m] = rsqrtf(var + BN_EPS);
            }
            __syncthreads();
        }

        // ---- BN + activation for this b (t<128) ----
        if (t < 128) {
            float v = g_pre[b*128 + m];
            v = fmaf(gamma[l*128 + m] * (v - smu[m]), srstd[m], beta[l*128 + m]);
            if (l < 5)
                v = fmaxf(v, 0.f);
            else
                v = -1.f + fmaxf(v + 0.5f, 0.f)*2.f - fmaxf(v - 0.5f, 0.f)*2.f;
            g_xeL[l*16384 + b*128 + m] = v;
            if (l == 5) out[b*128 + m] = v;
            xs[m] = v;
        }
        if (l == 5) break;
        __syncthreads();

        // ---- next-layer pre (dense, eighth-split) ----
        const int ln = l + 1;
        const float* Cb = g_C + ((size_t)ln*128 + b)*16384 + o*16*128 + m;
        float c[16];
#pragma unroll
        for (int j = 0; j < 16; j++) c[j] = Cb[j*128];
        float a0 = 0.f, a1 = 0.f, a2 = 0.f, a3 = 0.f;
#pragma unroll
        for (int j = 0; j < 16; j += 4) {
            a0 = fmaf(xs[o*16 + j    ], c[j    ], a0);
            a1 = fmaf(xs[o*16 + j + 1], c[j + 1], a1);
            a2 = fmaf(xs[o*16 + j + 2], c[j + 2], a2);
            a3 = fmaf(xs[o*16 + j + 3], c[j + 3], a3);
        }
        sp[t] = (a0 + a1) + (a2 + a3);
        __syncthreads();
        if (t < 128)
            g_pre[b*128 + m] = (((sp[m]+sp[m+128])+(sp[m+256]+sp[m+384]))
                              + ((sp[m+512]+sp[m+640])+(sp[m+768]+sp[m+896])))
                             + fmaf(xs[m], wx[ln*128 + m], -sd[ln*128 + m]);
        gridbar(128);
    }
}

// ---------------- K6: ALL-layer loss partials + final reduce ------------
__global__ void __launch_bounds__(256, 4)
k_loss_all(const float* __restrict__ B, const float* __restrict__ z,
           float* __restrict__ out,
           float s1, float s2, float s3, float s4, float s5)
{
    const int b   = blockIdx.y;
    const int ch  = blockIdx.x;
    const int tid = threadIdx.x;
    __shared__ float xs5[128][8];          // [n][l], padded
    __shared__ float wsum[5][8];
    __shared__ int   is_last;

    if (tid < 128) {
#pragma unroll
        for (int l = 0; l < 5; l++)
            xs5[tid][l] = g_xeL[(l+1)*16384 + b*128 + tid];
        xs5[tid][5] = 0.f; xs5[tid][6] = 0.f; xs5[tid][7] = 0.f;
    }
    __syncthreads();

    float acc[5][4];
#pragma unroll
    for (int l = 0; l < 5; l++)
#pragma unroll
        for (int j = 0; j < 4; j++) acc[l][j] = 0.f;

    const float4* Bb = reinterpret_cast<const float4*>(B)
                     + (size_t)b*262144 + ch*256 + tid;

    for (int n = 0; n < 128; n += 4) {
        float4 r0 = Bb[(size_t)(n  )*2048];
        float4 r1 = Bb[(size_t)(n+1)*2048];
        float4 r2 = Bb[(size_t)(n+2)*2048];
        float4 r3 = Bb[(size_t)(n+3)*2048];
#pragma unroll
        for (int j4 = 0; j4 < 4; j4++) {
            float4 rr = (j4 == 0) ? r0 : (j4 == 1) ? r1 : (j4 == 2) ? r2 : r3;
            const float4 xq = *reinterpret_cast<const float4*>(&xs5[n + j4][0]);
            const float x4 = xs5[n + j4][4];
            const float xl[5] = {xq.x, xq.y, xq.z, xq.w, x4};
#pragma unroll
            for (int l = 0; l < 5; l++) {
                acc[l][0] = fmaf(xl[l], rr.x, acc[l][0]);
                acc[l][1] = fmaf(xl[l], rr.y, acc[l][1]);
                acc[l][2] = fmaf(xl[l], rr.z, acc[l][2]);
                acc[l][3] = fmaf(xl[l], rr.w, acc[l][3]);
            }
        }
    }

    const float4 zv = reinterpret_cast<const float4*>(z)[(size_t)b*2048 + ch*256 + tid];
    const float zz[4] = {zv.x, zv.y, zv.z, zv.w};

#pragma unroll
    for (int l = 0; l < 5; l++) {
        float part = 0.f;
#pragma unroll
        for (int j = 0; j < 4; j++) {
            float e = zz[j] - acc[l][j];
            part = fmaf(e, e, part);
        }
#pragma unroll
        for (int o = 16; o > 0; o >>= 1)
            part += __shfl_down_sync(0xffffffffu, part, o);
        if ((tid & 31) == 0) wsum[l][tid >> 5] = part;
    }
    __syncthreads();
    if (tid == 0) {
#pragma unroll
        for (int l = 0; l < 5; l++) {
            float t = 0.f;
#pragma unroll
            for (int w = 0; w < 8; w++) t += wsum[l][w];
            g_part[(l+1)*1024 + b*8 + ch] = t;
        }
        __threadfence();
        unsigned tix = atomicAdd(&g_loss_tix, 1u);
        is_last = (tix == 1023u) ? 1 : 0;
        if (is_last) g_loss_tix = 0;   // self-reset for graph replay
    }
    __syncthreads();

    if (is_last) {
        __threadfence();               // all g_part writes now visible
        const int w    = tid >> 5;     // warp 0..7
        const int lane = tid & 31;
        if (tid == 0) out[16384] = 0.f;
        if (w < 5) {
            const float scl[5] = {s1, s2, s3, s4, s5};
            const float* P = g_part + (w + 1)*1024;
            float s = 0.f;
#pragma unroll
            for (int i = 0; i < 32; i++)
                s += P[i*32 + lane];
#pragma unroll
            for (int o = 16; o > 0; o >>= 1)
                s += __shfl_down_sync(0xffffffffu, s, o);
            if (lane == 0) out[16384 + w + 1] = scl[w] * s;
        }
    }
}

// ---------------- launch ------------------------------------------------
extern "C" void kernel_launch(void* const* d_in, const int* in_sizes, int n_in,
                              void* d_out, int out_size)
{
    (void)in_sizes; (void)n_in; (void)out_size;
    const float* BB    = (const float*)d_in[0];
    const float* zB    = (const float*)d_in[1];
    const float* z     = (const float*)d_in[3];
    const float* B     = (const float*)d_in[4];
    const float* x0    = (const float*)d_in[5];
    const float* w_x   = (const float*)d_in[6];
    const float* wKL   = (const float*)d_in[7];
    const float* gamma = (const float*)d_in[8];
    const float* beta  = (const float*)d_in[9];
    float* out = (float*)d_out;

    k_buildC<<<dim3(4,128), 256>>>(BB, wKL);
    k_chain<<<128, 1024>>>(x0, w_x, zB, wKL, gamma, beta, out);

    const float inv = 1.0f / 16384.0f;
    k_loss_all<<<dim3(8,128), 256>>>(B, z, out,
        10.0f * logf(2.0f) * inv,
        10.0f * logf(3.0f) * inv,
        10.0f * logf(4.0f) * inv,
        10.0f * logf(5.0f) * inv,
        10.0f * logf(6.0f) * inv);
}